// round 1
// baseline (speedup 1.0000x reference)
#include <cuda_runtime.h>
#include <math.h>

#define NH   12
#define D    64
#define SEQ  1024
#define BAT  4
#define HID  768
#define BS   4096      // BAT*SEQ
#define POS  512       // 2*span
#define SPAN 256

// -------- scratch (static device memory; no allocations) --------
__device__ float g_q[BS * HID];
__device__ float g_k[BS * HID];
__device__ float g_v[BS * HID];
__device__ float g_ctx[BS * HID];
__device__ float g_pre[BS * HID];
__device__ float g_posk[POS * HID];
__device__ float g_posq[POS * HID];
__device__ float g_c2p[(size_t)NH * BS * POS];   // [h][b*S+s][512]
__device__ float g_p2c[(size_t)NH * BS * POS];   // [h][b*S+t][512]
__device__ int   g_c2pidx[2048];
__device__ int   g_p2cidx[2048];

// -------- relative-position bucket table (matches numpy exactly) --------
__global__ void relb_kernel() {
    int i = blockIdx.x * blockDim.x + threadIdx.x;
    if (i >= 2047) return;
    int rel = i - 1023;
    const int mid = 128;   // BUCKETS/2
    int sgn = (rel > 0) - (rel < 0);
    float abs_pos = (rel < mid && rel > -mid) ? (float)(mid - 1) : (float)abs(rel);
    // numpy: numerator log in float32, divisor/mult in float64, ceil in float64
    float num32 = logf(abs_pos / 128.0f);
    double log_pos = ceil((double)num32 / log(511.0 / 128.0) * 127.0) + 128.0;
    long long bucket = (abs_pos <= 128.0f) ? (long long)rel
                                           : (long long)(log_pos * (double)sgn);
    int bi = (int)bucket;
    int c = bi + SPAN;  c = c < 0 ? 0 : (c > 2 * SPAN - 1 ? 2 * SPAN - 1 : c);
    int p = -bi + SPAN; p = p < 0 ? 0 : (p > 2 * SPAN - 1 ? 2 * SPAN - 1 : p);
    g_c2pidx[i] = c;
    g_p2cidx[i] = p;
}

// -------- generic GEMM: C[M,N] = A[M,K] @ Bw[N,K]^T (+bias) (+resid) --------
// 64x64 tile, 256 threads, 4x4 microtile, BK=16. z-batched via element strides.
__global__ void gemm_nt(const float* __restrict__ A, int lda, long long sAz,
                        const float* __restrict__ Bw, int ldb, long long sBz,
                        const float* __restrict__ bias,
                        const float* __restrict__ resid,
                        float* __restrict__ C, int ldc, long long sCz,
                        int M, int N, int K) {
    int z = blockIdx.z;
    A += (long long)z * sAz;
    Bw += (long long)z * sBz;
    C += (long long)z * sCz;
    int row0 = blockIdx.y * 64;
    int col0 = blockIdx.x * 64;
    __shared__ __align__(16) float As[16][68];
    __shared__ __align__(16) float Bs[16][68];
    int tid = threadIdx.x;
    int tx = tid & 15, ty = tid >> 4;
    float acc[4][4] = {};

    for (int k0 = 0; k0 < K; k0 += 16) {
#pragma unroll
        for (int i = 0; i < 4; i++) {
            int lin = tid + i * 256;
            int kk = lin & 15, m = lin >> 4;
            As[kk][m] = A[(long long)(row0 + m) * lda + k0 + kk];
            Bs[kk][m] = Bw[(long long)(col0 + m) * ldb + k0 + kk];
        }
        __syncthreads();
#pragma unroll
        for (int kk = 0; kk < 16; kk++) {
            float4 a4 = *reinterpret_cast<const float4*>(&As[kk][ty * 4]);
            float4 b4 = *reinterpret_cast<const float4*>(&Bs[kk][tx * 4]);
            float av[4] = {a4.x, a4.y, a4.z, a4.w};
            float bv[4] = {b4.x, b4.y, b4.z, b4.w};
#pragma unroll
            for (int i = 0; i < 4; i++)
#pragma unroll
                for (int j = 0; j < 4; j++)
                    acc[i][j] = fmaf(av[i], bv[j], acc[i][j]);
        }
        __syncthreads();
    }
#pragma unroll
    for (int i = 0; i < 4; i++) {
        int r = row0 + ty * 4 + i;
#pragma unroll
        for (int j = 0; j < 4; j++) {
            int c = col0 + tx * 4 + j;
            float v = acc[i][j];
            if (bias)  v += bias[c];
            if (resid) v += resid[(long long)r * ldc + c];
            C[(long long)r * ldc + c] = v;
        }
    }
}

// -------- scores = (q·k^T + c2p_gather + p2c_gather) / sqrt(192) --------
__global__ void scores_kernel(float* __restrict__ probs) {
    int bh = blockIdx.z;
    int b = bh / NH, h = bh % NH;
    int s0 = blockIdx.y * 64, t0 = blockIdx.x * 64;
    __shared__ __align__(16) float Qs[64][68];   // [d][s]
    __shared__ __align__(16) float Ks[64][68];   // [d][t]
    int tid = threadIdx.x;
    int tx = tid & 15, ty = tid >> 4;
    const float* qp = g_q + ((long long)(b * SEQ + s0)) * HID + h * D;
    const float* kp = g_k + ((long long)(b * SEQ + t0)) * HID + h * D;
#pragma unroll
    for (int i = 0; i < 16; i++) {
        int lin = tid + i * 256;
        int r = lin >> 6, d = lin & 63;
        Qs[d][r] = qp[(long long)r * HID + d];
        Ks[d][r] = kp[(long long)r * HID + d];
    }
    __syncthreads();
    float acc[4][4] = {};
#pragma unroll
    for (int d = 0; d < 64; d++) {
        float4 a4 = *reinterpret_cast<const float4*>(&Qs[d][ty * 4]);
        float4 b4 = *reinterpret_cast<const float4*>(&Ks[d][tx * 4]);
        float av[4] = {a4.x, a4.y, a4.z, a4.w};
        float bv[4] = {b4.x, b4.y, b4.z, b4.w};
#pragma unroll
        for (int i = 0; i < 4; i++)
#pragma unroll
            for (int j = 0; j < 4; j++)
                acc[i][j] = fmaf(av[i], bv[j], acc[i][j]);
    }
    const float inv = 1.0f / sqrtf(192.0f);
    long long c2p_base = ((long long)h * BS + (long long)b * SEQ) * POS;
#pragma unroll
    for (int i = 0; i < 4; i++) {
        int s = s0 + ty * 4 + i;
#pragma unroll
        for (int j = 0; j < 4; j++) {
            int t = t0 + tx * 4 + j;
            int dlt = s - t + 1023;
            float c2pv = g_c2p[c2p_base + (long long)s * POS + g_c2pidx[dlt]];
            float p2cv = g_p2c[c2p_base + (long long)t * POS + g_p2cidx[2046 - dlt]];
            probs[((long long)bh * SEQ + s) * SEQ + t] = (acc[i][j] + c2pv + p2cv) * inv;
        }
    }
}

// -------- softmax (in place, row = 1024) --------
__global__ void softmax_kernel(float* __restrict__ probs) {
    long long row = blockIdx.x;
    float* p = probs + row * SEQ;
    int tid = threadIdx.x;
    __shared__ float red[8];
    float v[4];
    float m = -1e30f;
#pragma unroll
    for (int k = 0; k < 4; k++) {
        v[k] = p[tid + k * 256];
        m = fmaxf(m, v[k]);
    }
#pragma unroll
    for (int o = 16; o; o >>= 1) m = fmaxf(m, __shfl_xor_sync(0xffffffffu, m, o));
    if ((tid & 31) == 0) red[tid >> 5] = m;
    __syncthreads();
    if (tid == 0) {
        float x = red[0];
#pragma unroll
        for (int i = 1; i < 8; i++) x = fmaxf(x, red[i]);
        red[0] = x;
    }
    __syncthreads();
    float rowmax = red[0];
    __syncthreads();
    float sum = 0.0f;
#pragma unroll
    for (int k = 0; k < 4; k++) {
        v[k] = expf(v[k] - rowmax);
        sum += v[k];
    }
#pragma unroll
    for (int o = 16; o; o >>= 1) sum += __shfl_xor_sync(0xffffffffu, sum, o);
    if ((tid & 31) == 0) red[tid >> 5] = sum;
    __syncthreads();
    if (tid == 0) {
        float x = 0.0f;
#pragma unroll
        for (int i = 0; i < 8; i++) x += red[i];
        red[0] = x;
    }
    __syncthreads();
    float rinv = 1.0f / red[0];
#pragma unroll
    for (int k = 0; k < 4; k++) p[tid + k * 256] = v[k] * rinv;
}

// -------- ctx = probs @ v  (per head: M=1024 s, N=64 d, K=1024 t) --------
__global__ void ctx_kernel(const float* __restrict__ probs) {
    int bh = blockIdx.y;
    int b = bh / NH, h = bh % NH;
    int s0 = blockIdx.x * 64;
    __shared__ __align__(16) float Ps[16][68];   // [t][s]
    __shared__ __align__(16) float Vs[16][68];   // [t][d]
    int tid = threadIdx.x;
    int tx = tid & 15, ty = tid >> 4;
    float acc[4][4] = {};
    const float* prow = probs + ((long long)bh * SEQ + s0) * SEQ;
    for (int k0 = 0; k0 < SEQ; k0 += 16) {
#pragma unroll
        for (int i = 0; i < 4; i++) {
            int lin = tid + i * 256;
            int kk = lin & 15, m = lin >> 4;
            Ps[kk][m] = prow[(long long)m * SEQ + k0 + kk];
            int n = lin & 63, kv = lin >> 6;
            Vs[kv][n] = g_v[((long long)(b * SEQ + k0 + kv)) * HID + h * D + n];
        }
        __syncthreads();
#pragma unroll
        for (int kk = 0; kk < 16; kk++) {
            float4 a4 = *reinterpret_cast<const float4*>(&Ps[kk][ty * 4]);
            float4 b4 = *reinterpret_cast<const float4*>(&Vs[kk][tx * 4]);
            float av[4] = {a4.x, a4.y, a4.z, a4.w};
            float bv[4] = {b4.x, b4.y, b4.z, b4.w};
#pragma unroll
            for (int i = 0; i < 4; i++)
#pragma unroll
                for (int j = 0; j < 4; j++)
                    acc[i][j] = fmaf(av[i], bv[j], acc[i][j]);
        }
        __syncthreads();
    }
#pragma unroll
    for (int i = 0; i < 4; i++) {
        int s = s0 + ty * 4 + i;
#pragma unroll
        for (int j = 0; j < 4; j++)
            g_ctx[((long long)(b * SEQ + s)) * HID + h * D + tx * 4 + j] = acc[i][j];
    }
}

// -------- layernorm over rows of g_pre --------
__global__ void ln_kernel(const float* __restrict__ lnw, const float* __restrict__ lnb,
                          float* __restrict__ out) {
    int row = blockIdx.x;
    const float* x = g_pre + (long long)row * HID;
    float* o = out + (long long)row * HID;
    int tid = threadIdx.x;
    __shared__ float red[8];
    float v[3];
    float s = 0.0f;
#pragma unroll
    for (int k = 0; k < 3; k++) {
        v[k] = x[tid + k * 256];
        s += v[k];
    }
#pragma unroll
    for (int o2 = 16; o2; o2 >>= 1) s += __shfl_xor_sync(0xffffffffu, s, o2);
    if ((tid & 31) == 0) red[tid >> 5] = s;
    __syncthreads();
    if (tid == 0) {
        float x2 = 0.0f;
#pragma unroll
        for (int i = 0; i < 8; i++) x2 += red[i];
        red[0] = x2;
    }
    __syncthreads();
    float mu = red[0] / (float)HID;
    __syncthreads();
    float sq = 0.0f;
#pragma unroll
    for (int k = 0; k < 3; k++) {
        float d = v[k] - mu;
        sq += d * d;
    }
#pragma unroll
    for (int o2 = 16; o2; o2 >>= 1) sq += __shfl_xor_sync(0xffffffffu, sq, o2);
    if ((tid & 31) == 0) red[tid >> 5] = sq;
    __syncthreads();
    if (tid == 0) {
        float x2 = 0.0f;
#pragma unroll
        for (int i = 0; i < 8; i++) x2 += red[i];
        red[0] = x2;
    }
    __syncthreads();
    float var = red[0] / (float)HID;
    float rstd = 1.0f / sqrtf(var + 1e-7f);
#pragma unroll
    for (int k = 0; k < 3; k++) {
        int c = tid + k * 256;
        o[c] = lnw[c] * (v[k] - mu) * rstd + lnb[c];
    }
}

extern "C" void kernel_launch(void* const* d_in, const int* in_sizes, int n_in,
                              void* d_out, int out_size) {
    const float* hs  = (const float*)d_in[0];
    const float* rel = (const float*)d_in[1];
    const float* Wq  = (const float*)d_in[2];
    const float* bq  = (const float*)d_in[3];
    const float* Wk  = (const float*)d_in[4];
    const float* bk  = (const float*)d_in[5];
    const float* Wv  = (const float*)d_in[6];
    const float* bv  = (const float*)d_in[7];
    const float* Wo  = (const float*)d_in[8];
    const float* bo  = (const float*)d_in[9];
    const float* lnw = (const float*)d_in[10];
    const float* lnb = (const float*)d_in[11];

    float* out   = (float*)d_out;
    float* probs = out + (size_t)BS * HID;

    float *pq, *pk, *pv, *pctx, *ppre, *pposk, *pposq, *pc2p, *pp2c;
    cudaGetSymbolAddress((void**)&pq, g_q);
    cudaGetSymbolAddress((void**)&pk, g_k);
    cudaGetSymbolAddress((void**)&pv, g_v);
    cudaGetSymbolAddress((void**)&pctx, g_ctx);
    cudaGetSymbolAddress((void**)&ppre, g_pre);
    cudaGetSymbolAddress((void**)&pposk, g_posk);
    cudaGetSymbolAddress((void**)&pposq, g_posq);
    cudaGetSymbolAddress((void**)&pc2p, g_c2p);
    cudaGetSymbolAddress((void**)&pp2c, g_p2c);

    relb_kernel<<<8, 256>>>();

    dim3 gProj(HID / 64, BS / 64, 1);
    gemm_nt<<<gProj, 256>>>(hs, HID, 0, Wq, HID, 0, bq, nullptr, pq, HID, 0, BS, HID, HID);
    gemm_nt<<<gProj, 256>>>(hs, HID, 0, Wk, HID, 0, bk, nullptr, pk, HID, 0, BS, HID, HID);
    gemm_nt<<<gProj, 256>>>(hs, HID, 0, Wv, HID, 0, bv, nullptr, pv, HID, 0, BS, HID, HID);

    dim3 gPos(HID / 64, POS / 64, 1);
    gemm_nt<<<gPos, 256>>>(rel, HID, 0, Wk, HID, 0, bk, nullptr, pposk, HID, 0, POS, HID, HID);
    gemm_nt<<<gPos, 256>>>(rel, HID, 0, Wq, HID, 0, bq, nullptr, pposq, HID, 0, POS, HID, HID);

    // c2p_att[h]: q_h (4096x64) @ pos_k_h^T (512x64)  -> [h][4096][512]
    dim3 gPA(POS / 64, BS / 64, NH);
    gemm_nt<<<gPA, 256>>>(pq, HID, D, pposk, HID, D, nullptr, nullptr,
                          pc2p, POS, (long long)BS * POS, BS, POS, D);
    gemm_nt<<<gPA, 256>>>(pk, HID, D, pposq, HID, D, nullptr, nullptr,
                          pp2c, POS, (long long)BS * POS, BS, POS, D);

    scores_kernel<<<dim3(SEQ / 64, SEQ / 64, BAT * NH), 256>>>(probs);
    softmax_kernel<<<BAT * NH * SEQ, 256>>>(probs);
    ctx_kernel<<<dim3(SEQ / 64, BAT * NH), 256>>>(probs);

    gemm_nt<<<gProj, 256>>>(pctx, HID, 0, Wo, HID, 0, bo, hs, ppre, HID, 0, BS, HID, HID);
    ln_kernel<<<BS, 256>>>(lnw, lnb, out);
}

// round 2
// speedup vs baseline: 1.9869x; 1.9869x over previous
#include <cuda_runtime.h>
#include <math.h>

#define NH   12
#define D    64
#define SEQ  1024
#define BAT  4
#define HID  768
#define BS   4096      // BAT*SEQ
#define POS  512       // 2*span
#define SPAN 256

// -------- scratch (static device memory; no allocations) --------
__device__ float g_q[BS * HID];
__device__ float g_k[BS * HID];
__device__ float g_v[BS * HID];          // TRANSPOSED per head: [b][h][d][s]
__device__ float g_ctx[BS * HID];
__device__ float g_pre[BS * HID];
__device__ float g_posk[POS * HID];
__device__ float g_posq[POS * HID];
__device__ float g_c2p[(size_t)NH * BS * POS];   // [h][b*S+s][512]
__device__ float g_p2c[(size_t)NH * BS * POS];   // [h][b*S+t][512]
__device__ int   g_c2pidx[2048];
__device__ int   g_p2cidx[2048];

// -------- relative-position bucket table (matches numpy exactly) --------
__global__ void relb_kernel() {
    int i = blockIdx.x * blockDim.x + threadIdx.x;
    if (i >= 2047) return;
    int rel = i - 1023;
    const int mid = 128;
    int sgn = (rel > 0) - (rel < 0);
    float abs_pos = (rel < mid && rel > -mid) ? (float)(mid - 1) : (float)abs(rel);
    float num32 = logf(abs_pos / 128.0f);
    double log_pos = ceil((double)num32 / log(511.0 / 128.0) * 127.0) + 128.0;
    long long bucket = (abs_pos <= 128.0f) ? (long long)rel
                                           : (long long)(log_pos * (double)sgn);
    int bi = (int)bucket;
    int c = bi + SPAN;  c = c < 0 ? 0 : (c > 2 * SPAN - 1 ? 2 * SPAN - 1 : c);
    int p = -bi + SPAN; p = p < 0 ? 0 : (p > 2 * SPAN - 1 ? 2 * SPAN - 1 : p);
    g_c2pidx[i] = c;
    g_p2cidx[i] = p;
}

// -------- tf32 helpers --------
__device__ __forceinline__ float f2tf(float x) {
    unsigned u;
    asm("cvt.rna.tf32.f32 %0, %1;" : "=r"(u) : "f"(x));
    return __uint_as_float(u);
}

__device__ __forceinline__ void mma_tf32(float* c, const unsigned* a, const unsigned* b) {
    asm volatile(
        "mma.sync.aligned.m16n8k8.row.col.f32.tf32.tf32.f32 "
        "{%0,%1,%2,%3},{%4,%5,%6,%7},{%8,%9},{%0,%1,%2,%3};"
        : "+f"(c[0]), "+f"(c[1]), "+f"(c[2]), "+f"(c[3])
        : "r"(a[0]), "r"(a[1]), "r"(a[2]), "r"(a[3]), "r"(b[0]), "r"(b[1]));
}

// -------- generic tensor-core NT GEMM body --------
// C[M,N] = A[M,K] @ B[N,K]^T, tile 128(m) x 64(n), BK=16, 256 threads (8 warps of 32x32).
// EPI: 0 = plain store, 1 = +bias, 2 = +bias+residual, 3 = +bias then scatter to vT layout
template<int EPI>
__device__ __forceinline__ void gemm_body(
    const float* __restrict__ A, int lda,
    const float* __restrict__ B, int ldb,
    const float* __restrict__ bias,
    const float* __restrict__ resid, int ldr,
    float* __restrict__ C, int ldc, int K)
{
    __shared__ __align__(16) float As[2][128][20];
    __shared__ __align__(16) float Bs[2][64][20];
    int tid = threadIdx.x;
    int wid = tid >> 5, lane = tid & 31;
    int quad = lane >> 2, qt = lane & 3;
    int wm = (wid >> 1) * 32;
    int wn = (wid & 1) * 32;
    long long row0 = (long long)blockIdx.y * 128;
    long long col0 = (long long)blockIdx.x * 64;

    float acc[2][4][4];
#pragma unroll
    for (int i = 0; i < 2; i++)
#pragma unroll
        for (int j = 0; j < 4; j++)
#pragma unroll
            for (int l = 0; l < 4; l++) acc[i][j][l] = 0.0f;

    const float* Ap = A + (row0 + (tid >> 2)) * (long long)lda + (tid & 3) * 4;
    const float* Bp = B + (col0 + (tid >> 2)) * (long long)ldb + (tid & 3) * 4;

    float4 ra0, ra1, rb;
    auto do_ldg = [&](long long ko) {
        ra0 = *reinterpret_cast<const float4*>(Ap + ko);
        ra1 = *reinterpret_cast<const float4*>(Ap + 64LL * lda + ko);
        rb  = *reinterpret_cast<const float4*>(Bp + ko);
    };
    auto do_sts = [&](int bf) {
        int m = tid >> 2, kq = (tid & 3) * 4;
        float4 t;
        t.x = f2tf(ra0.x); t.y = f2tf(ra0.y); t.z = f2tf(ra0.z); t.w = f2tf(ra0.w);
        *reinterpret_cast<float4*>(&As[bf][m][kq]) = t;
        t.x = f2tf(ra1.x); t.y = f2tf(ra1.y); t.z = f2tf(ra1.z); t.w = f2tf(ra1.w);
        *reinterpret_cast<float4*>(&As[bf][m + 64][kq]) = t;
        t.x = f2tf(rb.x); t.y = f2tf(rb.y); t.z = f2tf(rb.z); t.w = f2tf(rb.w);
        *reinterpret_cast<float4*>(&Bs[bf][m][kq]) = t;
    };
    auto do_comp = [&](int bf) {
#pragma unroll
        for (int kk = 0; kk < 16; kk += 8) {
            unsigned af[2][4], bfr[4][2];
#pragma unroll
            for (int mi = 0; mi < 2; mi++) {
                int r = wm + mi * 16 + quad;
                af[mi][0] = __float_as_uint(As[bf][r][kk + qt]);
                af[mi][1] = __float_as_uint(As[bf][r + 8][kk + qt]);
                af[mi][2] = __float_as_uint(As[bf][r][kk + qt + 4]);
                af[mi][3] = __float_as_uint(As[bf][r + 8][kk + qt + 4]);
            }
#pragma unroll
            for (int ni = 0; ni < 4; ni++) {
                int n = wn + ni * 8 + quad;
                bfr[ni][0] = __float_as_uint(Bs[bf][n][kk + qt]);
                bfr[ni][1] = __float_as_uint(Bs[bf][n][kk + qt + 4]);
            }
#pragma unroll
            for (int mi = 0; mi < 2; mi++)
#pragma unroll
                for (int ni = 0; ni < 4; ni++)
                    mma_tf32(acc[mi][ni], af[mi], bfr[ni]);
        }
    };

    int nst = K >> 4;
    do_ldg(0);
    do_sts(0);
    __syncthreads();
    int buf = 0;
    for (int s = 1; s < nst; s++) {
        do_ldg((long long)s * 16);
        do_sts(buf ^ 1);
        do_comp(buf);
        __syncthreads();
        buf ^= 1;
    }
    do_comp(buf);

    // epilogue
#pragma unroll
    for (int mi = 0; mi < 2; mi++) {
#pragma unroll
        for (int half = 0; half < 2; half++) {
            long long row = row0 + wm + mi * 16 + quad + half * 8;
#pragma unroll
            for (int ni = 0; ni < 4; ni++) {
                long long col = col0 + wn + ni * 8 + qt * 2;
                float v0 = acc[mi][ni][half * 2 + 0];
                float v1 = acc[mi][ni][half * 2 + 1];
                if (EPI >= 1) { v0 += bias[col]; v1 += bias[col + 1]; }
                if (EPI == 2) {
                    v0 += resid[row * ldr + col];
                    v1 += resid[row * ldr + col + 1];
                }
                if (EPI == 3) {
                    // scatter to vT layout [b][h][d][s]
                    int bb = (int)(row >> 10), ss = (int)(row & 1023);
                    int hh = (int)(col >> 6), dd = (int)(col & 63);
                    C[((((long long)bb * NH + hh) * D + dd) << 10) + ss] = v0;
                    hh = (int)((col + 1) >> 6); dd = (int)((col + 1) & 63);
                    C[((((long long)bb * NH + hh) * D + dd) << 10) + ss] = v1;
                } else {
                    *reinterpret_cast<float2*>(&C[row * ldc + col]) = make_float2(v0, v1);
                }
            }
        }
    }
}

// -------- GEMM wrappers --------
__global__ void __launch_bounds__(256) k_qk(const float* __restrict__ hs,
                                            const float* __restrict__ Wq, const float* __restrict__ bq,
                                            const float* __restrict__ Wk, const float* __restrict__ bk) {
    int z = blockIdx.z;
    const float* W = z == 0 ? Wq : Wk;
    const float* b = z == 0 ? bq : bk;
    float* Cc = z == 0 ? g_q : g_k;
    gemm_body<1>(hs, HID, W, HID, b, nullptr, 0, Cc, HID, HID);
}

__global__ void __launch_bounds__(256) k_v(const float* __restrict__ hs,
                                           const float* __restrict__ Wv, const float* __restrict__ bv) {
    gemm_body<3>(hs, HID, Wv, HID, bv, nullptr, 0, g_v, HID, HID);
}

__global__ void __launch_bounds__(256) k_pos(const float* __restrict__ rel,
                                             const float* __restrict__ Wq, const float* __restrict__ bq,
                                             const float* __restrict__ Wk, const float* __restrict__ bk) {
    int z = blockIdx.z;
    const float* W = z == 0 ? Wk : Wq;
    const float* b = z == 0 ? bk : bq;
    float* Cc = z == 0 ? g_posk : g_posq;
    gemm_body<1>(rel, HID, W, HID, b, nullptr, 0, Cc, HID, HID);
}

__global__ void __launch_bounds__(256) k_posatt() {
    int z = blockIdx.z;
    int h = z % NH;
    if (z < NH)
        gemm_body<0>(g_q + h * D, HID, g_posk + h * D, HID, nullptr, nullptr, 0,
                     g_c2p + (size_t)h * BS * POS, POS, D);
    else
        gemm_body<0>(g_k + h * D, HID, g_posq + h * D, HID, nullptr, nullptr, 0,
                     g_p2c + (size_t)h * BS * POS, POS, D);
}

__global__ void __launch_bounds__(256) k_scores(float* __restrict__ probs) {
    int z = blockIdx.z;
    int b = z / NH, h = z % NH;
    gemm_body<0>(g_q + (size_t)(b * SEQ) * HID + h * D, HID,
                 g_k + (size_t)(b * SEQ) * HID + h * D, HID,
                 nullptr, nullptr, 0,
                 probs + (size_t)z * SEQ * SEQ, SEQ, D);
}

__global__ void __launch_bounds__(256) k_ctx(const float* __restrict__ probs) {
    int z = blockIdx.z;
    int b = z / NH, h = z % NH;
    gemm_body<0>(probs + (size_t)z * SEQ * SEQ, SEQ,
                 g_v + (size_t)z * D * SEQ, SEQ,
                 nullptr, nullptr, 0,
                 g_ctx + (size_t)(b * SEQ) * HID + h * D, HID, SEQ);
}

__global__ void __launch_bounds__(256) k_out(const float* __restrict__ hs,
                                             const float* __restrict__ Wo, const float* __restrict__ bo) {
    gemm_body<2>(g_ctx, HID, Wo, HID, bo, hs, HID, g_pre, HID, HID);
}

// -------- softmax with fused rel-pos gathers + scale (in place) --------
__global__ void softmax_kernel(float* __restrict__ probs) {
    int s = blockIdx.x;
    int bh = blockIdx.y;
    int b = bh / NH, h = bh % NH;
    float* p = probs + ((long long)bh * SEQ + s) * SEQ;
    __shared__ float c2ps[POS];
    __shared__ float red[8];
    int tid = threadIdx.x;
    long long cbase = ((long long)h * BS + b * SEQ + s) * POS;
    c2ps[tid] = g_c2p[cbase + tid];
    c2ps[tid + 256] = g_c2p[cbase + tid + 256];
    long long pbase = ((long long)h * BS + (long long)b * SEQ) * POS;
    __syncthreads();
    const float inv = rsqrtf(192.0f);
    float v[4];
    float m = -1e30f;
#pragma unroll
    for (int k = 0; k < 4; k++) {
        int t = tid + k * 256;
        int dlt = s - t + 1023;
        float x = p[t] + c2ps[g_c2pidx[dlt]]
                + g_p2c[pbase + (long long)t * POS + g_p2cidx[2046 - dlt]];
        v[k] = x * inv;
        m = fmaxf(m, v[k]);
    }
#pragma unroll
    for (int o = 16; o; o >>= 1) m = fmaxf(m, __shfl_xor_sync(0xffffffffu, m, o));
    if ((tid & 31) == 0) red[tid >> 5] = m;
    __syncthreads();
    if (tid == 0) {
        float x = red[0];
#pragma unroll
        for (int i = 1; i < 8; i++) x = fmaxf(x, red[i]);
        red[0] = x;
    }
    __syncthreads();
    float rowmax = red[0];
    __syncthreads();
    float sum = 0.0f;
#pragma unroll
    for (int k = 0; k < 4; k++) {
        v[k] = expf(v[k] - rowmax);
        sum += v[k];
    }
#pragma unroll
    for (int o = 16; o; o >>= 1) sum += __shfl_xor_sync(0xffffffffu, sum, o);
    if ((tid & 31) == 0) red[tid >> 5] = sum;
    __syncthreads();
    if (tid == 0) {
        float x = 0.0f;
#pragma unroll
        for (int i = 0; i < 8; i++) x += red[i];
        red[0] = x;
    }
    __syncthreads();
    float rinv = 1.0f / red[0];
#pragma unroll
    for (int k = 0; k < 4; k++) p[tid + k * 256] = v[k] * rinv;
}

// -------- layernorm over rows of g_pre --------
__global__ void ln_kernel(const float* __restrict__ lnw, const float* __restrict__ lnb,
                          float* __restrict__ out) {
    int row = blockIdx.x;
    const float* x = g_pre + (long long)row * HID;
    float* o = out + (long long)row * HID;
    int tid = threadIdx.x;
    __shared__ float red[8];
    float v[3];
    float s = 0.0f;
#pragma unroll
    for (int k = 0; k < 3; k++) {
        v[k] = x[tid + k * 256];
        s += v[k];
    }
#pragma unroll
    for (int o2 = 16; o2; o2 >>= 1) s += __shfl_xor_sync(0xffffffffu, s, o2);
    if ((tid & 31) == 0) red[tid >> 5] = s;
    __syncthreads();
    if (tid == 0) {
        float x2 = 0.0f;
#pragma unroll
        for (int i = 0; i < 8; i++) x2 += red[i];
        red[0] = x2;
    }
    __syncthreads();
    float mu = red[0] / (float)HID;
    __syncthreads();
    float sq = 0.0f;
#pragma unroll
    for (int k = 0; k < 3; k++) {
        float d = v[k] - mu;
        sq += d * d;
    }
#pragma unroll
    for (int o2 = 16; o2; o2 >>= 1) sq += __shfl_xor_sync(0xffffffffu, sq, o2);
    if ((tid & 31) == 0) red[tid >> 5] = sq;
    __syncthreads();
    if (tid == 0) {
        float x2 = 0.0f;
#pragma unroll
        for (int i = 0; i < 8; i++) x2 += red[i];
        red[0] = x2;
    }
    __syncthreads();
    float var = red[0] / (float)HID;
    float rstd = 1.0f / sqrtf(var + 1e-7f);
#pragma unroll
    for (int k = 0; k < 3; k++) {
        int c = tid + k * 256;
        o[c] = lnw[c] * (v[k] - mu) * rstd + lnb[c];
    }
}

extern "C" void kernel_launch(void* const* d_in, const int* in_sizes, int n_in,
                              void* d_out, int out_size) {
    const float* hs  = (const float*)d_in[0];
    const float* rel = (const float*)d_in[1];
    const float* Wq  = (const float*)d_in[2];
    const float* bq  = (const float*)d_in[3];
    const float* Wk  = (const float*)d_in[4];
    const float* bk  = (const float*)d_in[5];
    const float* Wv  = (const float*)d_in[6];
    const float* bv  = (const float*)d_in[7];
    const float* Wo  = (const float*)d_in[8];
    const float* bo  = (const float*)d_in[9];
    const float* lnw = (const float*)d_in[10];
    const float* lnb = (const float*)d_in[11];

    float* out   = (float*)d_out;
    float* probs = out + (size_t)BS * HID;

    relb_kernel<<<8, 256>>>();

    k_qk<<<dim3(HID / 64, BS / 128, 2), 256>>>(hs, Wq, bq, Wk, bk);
    k_v<<<dim3(HID / 64, BS / 128, 1), 256>>>(hs, Wv, bv);
    k_pos<<<dim3(HID / 64, POS / 128, 2), 256>>>(rel, Wq, bq, Wk, bk);
    k_posatt<<<dim3(POS / 64, BS / 128, 2 * NH), 256>>>();
    k_scores<<<dim3(SEQ / 64, SEQ / 128, BAT * NH), 256>>>(probs);
    softmax_kernel<<<dim3(SEQ, BAT * NH), 256>>>(probs);
    k_ctx<<<dim3(1, SEQ / 128, BAT * NH), 256>>>(probs);
    k_out<<<dim3(HID / 64, BS / 128, 1), 256>>>(hs, Wo, bo);
    ln_kernel<<<BS, 256>>>(lnw, lnb, out);
}

// round 3
// speedup vs baseline: 2.3614x; 1.1885x over previous
#include <cuda_runtime.h>
#include <math.h>

#define NH   12
#define D    64
#define SEQ  1024
#define BAT  4
#define HID  768
#define BS   4096      // BAT*SEQ
#define POS  512       // 2*span
#define SPAN 256

// -------- scratch (static device memory; no allocations) --------
__device__ float g_q[BS * HID];
__device__ float g_k[BS * HID];
__device__ float g_v[BS * HID];          // TRANSPOSED per head: [b][h][d][s]
__device__ float g_ctx[BS * HID];
__device__ float g_pre[BS * HID];
__device__ float g_posk[POS * HID];
__device__ float g_posq[POS * HID];
__device__ float g_c2p[(size_t)NH * BS * POS];    // [h][b*S+s][512]
__device__ float g_p2cT[(size_t)NH * POS * BS];   // [h][bucket][b*S+t]  (transposed!)
__device__ int   g_c2pidx[2048];
__device__ int   g_p2cidx[2048];

// -------- relative-position bucket table (matches numpy exactly) --------
__global__ void relb_kernel() {
    int i = blockIdx.x * blockDim.x + threadIdx.x;
    if (i >= 2047) return;
    int rel = i - 1023;
    const int mid = 128;
    int sgn = (rel > 0) - (rel < 0);
    float abs_pos = (rel < mid && rel > -mid) ? (float)(mid - 1) : (float)abs(rel);
    float num32 = logf(abs_pos / 128.0f);
    double log_pos = ceil((double)num32 / log(511.0 / 128.0) * 127.0) + 128.0;
    long long bucket = (abs_pos <= 128.0f) ? (long long)rel
                                           : (long long)(log_pos * (double)sgn);
    int bi = (int)bucket;
    int c = bi + SPAN;  c = c < 0 ? 0 : (c > 2 * SPAN - 1 ? 2 * SPAN - 1 : c);
    int p = -bi + SPAN; p = p < 0 ? 0 : (p > 2 * SPAN - 1 ? 2 * SPAN - 1 : p);
    g_c2pidx[i] = c;
    g_p2cidx[i] = p;
}

// -------- tf32 helpers --------
__device__ __forceinline__ float f2tf(float x) {
    unsigned u;
    asm("cvt.rna.tf32.f32 %0, %1;" : "=r"(u) : "f"(x));
    return __uint_as_float(u);
}

__device__ __forceinline__ void mma_tf32(float* c, const unsigned* a, const unsigned* b) {
    asm volatile(
        "mma.sync.aligned.m16n8k8.row.col.f32.tf32.tf32.f32 "
        "{%0,%1,%2,%3},{%4,%5,%6,%7},{%8,%9},{%0,%1,%2,%3};"
        : "+f"(c[0]), "+f"(c[1]), "+f"(c[2]), "+f"(c[3])
        : "r"(a[0]), "r"(a[1]), "r"(a[2]), "r"(a[3]), "r"(b[0]), "r"(b[1]));
}

// -------- generic tensor-core NT GEMM body --------
// C[TM x 64] tile of C[M,N] = A[M,K] @ B[N,K]^T. 256 threads. BK=16, double buffered,
// mainloop ordered ldg(next) -> mma(cur) -> sts(next) so MMAs hide GMEM latency.
// EPI: 0 plain, 1 +bias, 2 +bias+resid, 3 +bias then scatter to vT [b][h][d][s]
template<int EPI, int TM>
__device__ __forceinline__ void gemm_body(
    const float* __restrict__ A, int lda,
    const float* __restrict__ B, int ldb,
    const float* __restrict__ bias,
    const float* __restrict__ resid, int ldr,
    float* __restrict__ C, long long ldc, int K,
    int row0, int col0)
{
    constexpr int MI = TM / 64;   // 2 for TM=128, 1 for TM=64
    __shared__ __align__(16) float As[2][TM][20];
    __shared__ __align__(16) float Bs[2][64][20];
    int tid = threadIdx.x;
    int wid = tid >> 5, lane = tid & 31;
    int quad = lane >> 2, qt = lane & 3;
    int wm, wn;
    if (TM == 128) { wm = (wid >> 1) * 32; wn = (wid & 1) * 32; }
    else           { wm = (wid & 3) * 16;  wn = (wid >> 2) * 32; }

    float acc[MI][4][4];
#pragma unroll
    for (int i = 0; i < MI; i++)
#pragma unroll
        for (int j = 0; j < 4; j++)
#pragma unroll
            for (int l = 0; l < 4; l++) acc[i][j][l] = 0.0f;

    const float* Ap = A + ((long long)row0 + (tid >> 2)) * lda + (tid & 3) * 4;
    const float* Bp = B + ((long long)col0 + (tid >> 2)) * ldb + (tid & 3) * 4;

    float4 ra0, ra1, rb;
    auto do_ldg = [&](long long ko) {
        ra0 = *reinterpret_cast<const float4*>(Ap + ko);
        if (TM == 128) ra1 = *reinterpret_cast<const float4*>(Ap + 64LL * lda + ko);
        rb  = *reinterpret_cast<const float4*>(Bp + ko);
    };
    auto do_sts = [&](int bf) {
        int m = tid >> 2, kq = (tid & 3) * 4;
        float4 t;
        t.x = f2tf(ra0.x); t.y = f2tf(ra0.y); t.z = f2tf(ra0.z); t.w = f2tf(ra0.w);
        *reinterpret_cast<float4*>(&As[bf][m][kq]) = t;
        if (TM == 128) {
            t.x = f2tf(ra1.x); t.y = f2tf(ra1.y); t.z = f2tf(ra1.z); t.w = f2tf(ra1.w);
            *reinterpret_cast<float4*>(&As[bf][m + 64][kq]) = t;
        }
        t.x = f2tf(rb.x); t.y = f2tf(rb.y); t.z = f2tf(rb.z); t.w = f2tf(rb.w);
        *reinterpret_cast<float4*>(&Bs[bf][m][kq]) = t;
    };
    auto do_comp = [&](int bf) {
#pragma unroll
        for (int kk = 0; kk < 16; kk += 8) {
            unsigned af[MI][4], bfr[4][2];
#pragma unroll
            for (int mi = 0; mi < MI; mi++) {
                int r = wm + mi * 16 + quad;
                af[mi][0] = __float_as_uint(As[bf][r][kk + qt]);
                af[mi][1] = __float_as_uint(As[bf][r + 8][kk + qt]);
                af[mi][2] = __float_as_uint(As[bf][r][kk + qt + 4]);
                af[mi][3] = __float_as_uint(As[bf][r + 8][kk + qt + 4]);
            }
#pragma unroll
            for (int ni = 0; ni < 4; ni++) {
                int n = wn + ni * 8 + quad;
                bfr[ni][0] = __float_as_uint(Bs[bf][n][kk + qt]);
                bfr[ni][1] = __float_as_uint(Bs[bf][n][kk + qt + 4]);
            }
#pragma unroll
            for (int mi = 0; mi < MI; mi++)
#pragma unroll
                for (int ni = 0; ni < 4; ni++)
                    mma_tf32(acc[mi][ni], af[mi], bfr[ni]);
        }
    };

    int nst = K >> 4;
    do_ldg(0);
    do_sts(0);
    __syncthreads();
    int buf = 0;
    for (int s = 1; s < nst; s++) {
        do_ldg((long long)s * 16);   // issue next-stage loads
        do_comp(buf);                // MMAs on current stage cover load latency
        do_sts(buf ^ 1);             // loads have landed by now
        __syncthreads();
        buf ^= 1;
    }
    do_comp(buf);

    // epilogue
#pragma unroll
    for (int mi = 0; mi < MI; mi++) {
#pragma unroll
        for (int half = 0; half < 2; half++) {
            long long row = row0 + wm + mi * 16 + quad + half * 8;
#pragma unroll
            for (int ni = 0; ni < 4; ni++) {
                long long col = col0 + wn + ni * 8 + qt * 2;
                float v0 = acc[mi][ni][half * 2 + 0];
                float v1 = acc[mi][ni][half * 2 + 1];
                if (EPI >= 1) { v0 += bias[col]; v1 += bias[col + 1]; }
                if (EPI == 2) {
                    v0 += resid[row * ldr + col];
                    v1 += resid[row * ldr + col + 1];
                }
                if (EPI == 3) {
                    int bb = (int)(row >> 10), ss = (int)(row & 1023);
                    int hh = (int)(col >> 6), dd = (int)(col & 63);
                    C[((((long long)bb * NH + hh) * D + dd) << 10) + ss] = v0;
                    hh = (int)((col + 1) >> 6); dd = (int)((col + 1) & 63);
                    C[((((long long)bb * NH + hh) * D + dd) << 10) + ss] = v1;
                } else {
                    *reinterpret_cast<float2*>(&C[row * ldc + col]) = make_float2(v0, v1);
                }
            }
        }
    }
}

// -------- merged projection kernel: q,k,v,posk,posq in one launch --------
__global__ void __launch_bounds__(256) k_proj(
    const float* __restrict__ hs, const float* __restrict__ rel,
    const float* __restrict__ Wq, const float* __restrict__ bq,
    const float* __restrict__ Wk, const float* __restrict__ bk,
    const float* __restrict__ Wv, const float* __restrict__ bv)
{
    int y = blockIdx.y;
    int col0 = blockIdx.x * 64;
    if (y < 32)
        gemm_body<1, 128>(hs, HID, Wq, HID, bq, nullptr, 0, g_q, HID, HID, y * 128, col0);
    else if (y < 64)
        gemm_body<1, 128>(hs, HID, Wk, HID, bk, nullptr, 0, g_k, HID, HID, (y - 32) * 128, col0);
    else if (y < 96)
        gemm_body<3, 128>(hs, HID, Wv, HID, bv, nullptr, 0, g_v, HID, HID, (y - 64) * 128, col0);
    else if (y < 100)
        gemm_body<1, 128>(rel, HID, Wk, HID, bk, nullptr, 0, g_posk, HID, HID, (y - 96) * 128, col0);
    else
        gemm_body<1, 128>(rel, HID, Wq, HID, bq, nullptr, 0, g_posq, HID, HID, (y - 100) * 128, col0);
}

// -------- pos-att: c2p [h][s][bucket] and p2cT [h][bucket][t] in one launch --------
__global__ void __launch_bounds__(256) k_posatt() {
    int z = blockIdx.x;
    if (z < 3072) {                           // c2p: M=4096, N=512 per head
        int h = z >> 8, r = z & 255;
        gemm_body<0, 128>(g_q + h * D, HID, g_posk + h * D, HID, nullptr, nullptr, 0,
                          g_c2p + (size_t)h * BS * POS, POS, D,
                          (r >> 3) * 128, (r & 7) * 64);
    } else {                                  // p2cT: M=512, N=4096 per head
        z -= 3072;
        int h = z >> 8, r = z & 255;
        gemm_body<0, 128>(g_posq + h * D, HID, g_k + h * D, HID, nullptr, nullptr, 0,
                          g_p2cT + (size_t)h * POS * BS, BS, D,
                          (r >> 6) * 128, (r & 63) * 64);
    }
}

__global__ void __launch_bounds__(256) k_scores(float* __restrict__ probs) {
    int z = blockIdx.z;
    int b = z / NH, h = z % NH;
    gemm_body<0, 128>(g_q + (size_t)(b * SEQ) * HID + h * D, HID,
                      g_k + (size_t)(b * SEQ) * HID + h * D, HID,
                      nullptr, nullptr, 0,
                      probs + (size_t)z * SEQ * SEQ, SEQ, D,
                      blockIdx.y * 128, blockIdx.x * 64);
}

__global__ void __launch_bounds__(256) k_ctx(const float* __restrict__ probs) {
    int z = blockIdx.y;
    int b = z / NH, h = z % NH;
    gemm_body<0, 64>(probs + (size_t)z * SEQ * SEQ, SEQ,
                     g_v + (size_t)z * D * SEQ, SEQ,
                     nullptr, nullptr, 0,
                     g_ctx + (size_t)(b * SEQ) * HID + h * D, HID, SEQ,
                     blockIdx.x * 64, 0);
}

__global__ void __launch_bounds__(256) k_out(const float* __restrict__ hs,
                                             const float* __restrict__ Wo, const float* __restrict__ bo) {
    gemm_body<2, 128>(g_ctx, HID, Wo, HID, bo, hs, HID, g_pre, HID, HID,
                      blockIdx.y * 128, blockIdx.x * 64);
}

// -------- softmax with fused rel-pos gathers + scale (in place) --------
__global__ void softmax_kernel(float* __restrict__ probs) {
    int s = blockIdx.x;
    int bh = blockIdx.y;
    int b = bh / NH, h = bh % NH;
    float* p = probs + ((long long)bh * SEQ + s) * SEQ;
    __shared__ float c2ps[POS];
    __shared__ float red[8];
    int tid = threadIdx.x;
    long long cbase = ((long long)h * BS + b * SEQ + s) * POS;
    c2ps[tid] = g_c2p[cbase + tid];
    c2ps[tid + 256] = g_c2p[cbase + tid + 256];
    long long pTbase = (long long)h * POS * BS + (long long)b * SEQ;
    __syncthreads();
    const float inv = rsqrtf(192.0f);
    float v[4];
    float m = -1e30f;
#pragma unroll
    for (int k = 0; k < 4; k++) {
        int t = tid + k * 256;
        int dlt = s - t + 1023;
        // p2cT gather: idx nearly constant across warp, t contiguous -> coalesced
        float x = p[t] + c2ps[g_c2pidx[dlt]]
                + g_p2cT[pTbase + (long long)g_p2cidx[2046 - dlt] * BS + t];
        v[k] = x * inv;
        m = fmaxf(m, v[k]);
    }
#pragma unroll
    for (int o = 16; o; o >>= 1) m = fmaxf(m, __shfl_xor_sync(0xffffffffu, m, o));
    if ((tid & 31) == 0) red[tid >> 5] = m;
    __syncthreads();
    if (tid == 0) {
        float x = red[0];
#pragma unroll
        for (int i = 1; i < 8; i++) x = fmaxf(x, red[i]);
        red[0] = x;
    }
    __syncthreads();
    float rowmax = red[0];
    __syncthreads();
    float sum = 0.0f;
#pragma unroll
    for (int k = 0; k < 4; k++) {
        v[k] = expf(v[k] - rowmax);
        sum += v[k];
    }
#pragma unroll
    for (int o = 16; o; o >>= 1) sum += __shfl_xor_sync(0xffffffffu, sum, o);
    if ((tid & 31) == 0) red[tid >> 5] = sum;
    __syncthreads();
    if (tid == 0) {
        float x = 0.0f;
#pragma unroll
        for (int i = 0; i < 8; i++) x += red[i];
        red[0] = x;
    }
    __syncthreads();
    float rinv = 1.0f / red[0];
#pragma unroll
    for (int k = 0; k < 4; k++) p[tid + k * 256] = v[k] * rinv;
}

// -------- layernorm over rows of g_pre --------
__global__ void ln_kernel(const float* __restrict__ lnw, const float* __restrict__ lnb,
                          float* __restrict__ out) {
    int row = blockIdx.x;
    const float* x = g_pre + (long long)row * HID;
    float* o = out + (long long)row * HID;
    int tid = threadIdx.x;
    __shared__ float red[8];
    float v[3];
    float s = 0.0f;
#pragma unroll
    for (int k = 0; k < 3; k++) {
        v[k] = x[tid + k * 256];
        s += v[k];
    }
#pragma unroll
    for (int o2 = 16; o2; o2 >>= 1) s += __shfl_xor_sync(0xffffffffu, s, o2);
    if ((tid & 31) == 0) red[tid >> 5] = s;
    __syncthreads();
    if (tid == 0) {
        float x2 = 0.0f;
#pragma unroll
        for (int i = 0; i < 8; i++) x2 += red[i];
        red[0] = x2;
    }
    __syncthreads();
    float mu = red[0] / (float)HID;
    __syncthreads();
    float sq = 0.0f;
#pragma unroll
    for (int k = 0; k < 3; k++) {
        float d = v[k] - mu;
        sq += d * d;
    }
#pragma unroll
    for (int o2 = 16; o2; o2 >>= 1) sq += __shfl_xor_sync(0xffffffffu, sq, o2);
    if ((tid & 31) == 0) red[tid >> 5] = sq;
    __syncthreads();
    if (tid == 0) {
        float x2 = 0.0f;
#pragma unroll
        for (int i = 0; i < 8; i++) x2 += red[i];
        red[0] = x2;
    }
    __syncthreads();
    float var = red[0] / (float)HID;
    float rstd = 1.0f / sqrtf(var + 1e-7f);
#pragma unroll
    for (int k = 0; k < 3; k++) {
        int c = tid + k * 256;
        o[c] = lnw[c] * (v[k] - mu) * rstd + lnb[c];
    }
}

extern "C" void kernel_launch(void* const* d_in, const int* in_sizes, int n_in,
                              void* d_out, int out_size) {
    const float* hs  = (const float*)d_in[0];
    const float* rel = (const float*)d_in[1];
    const float* Wq  = (const float*)d_in[2];
    const float* bq  = (const float*)d_in[3];
    const float* Wk  = (const float*)d_in[4];
    const float* bk  = (const float*)d_in[5];
    const float* Wv  = (const float*)d_in[6];
    const float* bv  = (const float*)d_in[7];
    const float* Wo  = (const float*)d_in[8];
    const float* bo  = (const float*)d_in[9];
    const float* lnw = (const float*)d_in[10];
    const float* lnb = (const float*)d_in[11];

    float* out   = (float*)d_out;
    float* probs = out + (size_t)BS * HID;

    relb_kernel<<<8, 256>>>();
    k_proj<<<dim3(HID / 64, 104), 256>>>(hs, rel, Wq, bq, Wk, bk, Wv, bv);
    k_posatt<<<6144, 256>>>();
    k_scores<<<dim3(SEQ / 64, SEQ / 128, BAT * NH), 256>>>(probs);
    softmax_kernel<<<dim3(SEQ, BAT * NH), 256>>>(probs);
    k_ctx<<<dim3(SEQ / 64, BAT * NH), 256>>>(probs);
    k_out<<<dim3(HID / 64, BS / 128), 256>>>(hs, Wo, bo);
    ln_kernel<<<BS, 256>>>(lnw, lnb, out);
}